// round 1
// baseline (speedup 1.0000x reference)
#include <cuda_runtime.h>
#include <cuda_bf16.h>

// Problem shape (fixed by the dataset)
#define Bv 8
#define Cv 256
#define Lv 4096
#define Kv 8

// Precomputed softmax time-weights: w[b][l][k], 8*4096*8 floats = 1 MB.
// Stays L2-resident; reused by all 256 channels of each batch.
__device__ float g_w[Bv * Lv * Kv];

// ---------------------------------------------------------------------------
// Kernel 1: w[b,l,k] = softmax_k( dt[b,l-k] - dt[b,l] ), with the reference's
// BIG-sentinel semantics: for l < K-1 the masked taps dominate the softmax max
// so all *valid* weights are exactly 0 -> average_time == 0 there. We encode
// that by writing w = 0 for all k when l < K-1.
// ---------------------------------------------------------------------------
__global__ void __launch_bounds__(256) compute_w_kernel(const float* __restrict__ dt) {
    int idx = blockIdx.x * blockDim.x + threadIdx.x;   // idx = b*L + l
    if (idx >= Bv * Lv) return;
    int l = idx & (Lv - 1);
    float* wout = &g_w[(size_t)idx * Kv];

    if (l < Kv - 1) {
#pragma unroll
        for (int k = 0; k < Kv; k++) wout[k] = 0.0f;
        return;
    }

    float base = dt[idx];
    float d[Kv];
    float mx = -1e30f;
#pragma unroll
    for (int k = 0; k < Kv; k++) {
        d[k] = dt[idx - k] - base;
        mx = fmaxf(mx, d[k]);
    }
    float s = 0.0f;
#pragma unroll
    for (int k = 0; k < Kv; k++) {
        d[k] = __expf(d[k] - mx);
        s += d[k];
    }
    float inv = 1.0f / s;
#pragma unroll
    for (int k = 0; k < Kv; k++) wout[k] = d[k] * inv;
}

// ---------------------------------------------------------------------------
// Kernel 2: one CTA per (b,c) row.
//   Pass 1: stage x row in smem; compute at[l], ap[l] into smem; accumulate
//           Gram scalars g00 = <at,at>, g01 = <at,ap>, g11 = <ap,ap>.
//   Reduce: block reduction -> 2x2 softmax -> scalar coefficients ca, cb.
//   Pass 2: out[l] = ca*at[l] + cb*ap[l].
// Dynamic smem layout: sx[Lv+Kv] (x with 8-zero left pad) | sat[Lv] | sap[Lv]
// = 49184 bytes.
// ---------------------------------------------------------------------------
#define SMEM_BYTES ((Lv + Kv + Lv + Lv) * 4)

__global__ void __launch_bounds__(256) fused_kernel(
    const float* __restrict__ x,
    const float* __restrict__ kt,
    float* __restrict__ out)
{
    extern __shared__ float smem[];
    float* sx  = smem;              // [Lv + Kv], sx[Kv + l] = x[l]
    float* sat = sx + (Lv + Kv);    // [Lv]
    float* sap = sat + Lv;          // [Lv]
    __shared__ float sred[3 * 8];
    __shared__ float scoef[2];

    const int bc = blockIdx.x;           // b*C + c
    const int b  = bc >> 8;              // Cv = 256
    const float* xrow = x + (size_t)bc * Lv;
    float* orow = out + (size_t)bc * Lv;
    const float4* wrow = (const float4*)&g_w[(size_t)b * Lv * Kv];

    const int tid = threadIdx.x;

    // Stage x row (vectorized), zero left pad.
    if (tid < Kv) sx[tid] = 0.0f;
    {
        float4* sx4 = (float4*)(sx + Kv);          // Kv*4 = 32B offset, 16B aligned
        const float4* x4 = (const float4*)xrow;
#pragma unroll
        for (int i = 0; i < Lv / 4 / 256; i++)
            sx4[tid + i * 256] = x4[tid + i * 256];
    }

    float ktr[Kv];
#pragma unroll
    for (int k = 0; k < Kv; k++) ktr[k] = __ldg(&kt[k]);

    __syncthreads();

    // Pass 1: at/ap + Gram partials
    float g00 = 0.0f, g01 = 0.0f, g11 = 0.0f;
#pragma unroll
    for (int i = 0; i < Lv / 256; i++) {
        int l = tid + i * 256;
        float4 w0 = wrow[l * 2];
        float4 w1 = wrow[l * 2 + 1];
        float wv[Kv] = {w0.x, w0.y, w0.z, w0.w, w1.x, w1.y, w1.z, w1.w};
        float at = 0.0f, ap = 0.0f;
#pragma unroll
        for (int k = 0; k < Kv; k++) {
            float xv = sx[Kv + l - k];
            at = fmaf(wv[k],  xv, at);
            ap = fmaf(ktr[k], xv, ap);
        }
        sat[l] = at;
        sap[l] = ap;
        g00 = fmaf(at, at, g00);
        g01 = fmaf(at, ap, g01);
        g11 = fmaf(ap, ap, g11);
    }

    // Block reduction of the three Gram scalars.
#pragma unroll
    for (int o = 16; o > 0; o >>= 1) {
        g00 += __shfl_xor_sync(0xffffffffu, g00, o);
        g01 += __shfl_xor_sync(0xffffffffu, g01, o);
        g11 += __shfl_xor_sync(0xffffffffu, g11, o);
    }
    int wid = tid >> 5, lid = tid & 31;
    if (lid == 0) {
        sred[wid]      = g00;
        sred[8 + wid]  = g01;
        sred[16 + wid] = g11;
    }
    __syncthreads();
    if (tid == 0) {
        float G00 = 0.0f, G01 = 0.0f, G11 = 0.0f;
#pragma unroll
        for (int i = 0; i < 8; i++) {
            G00 += sred[i];
            G01 += sred[8 + i];
            G11 += sred[16 + i];
        }
        // scores row0 = softmax([G00, G01]); row1 = softmax([G01, G11])
        // out = 0.5*((s00+s10)*at + (s01+s11)*ap)
        float s00 = 1.0f / (1.0f + __expf(G01 - G00));
        float s10 = 1.0f / (1.0f + __expf(G11 - G01));
        scoef[0] = 0.5f * (s00 + s10);
        scoef[1] = 0.5f * ((1.0f - s00) + (1.0f - s10));
    }
    __syncthreads();

    // Pass 2: output
    const float ca = scoef[0], cb = scoef[1];
#pragma unroll
    for (int i = 0; i < Lv / 256; i++) {
        int l = tid + i * 256;
        orow[l] = fmaf(ca, sat[l], cb * sap[l]);
    }
}

// ---------------------------------------------------------------------------
extern "C" void kernel_launch(void* const* d_in, const int* in_sizes, int n_in,
                              void* d_out, int out_size) {
    const float* x  = (const float*)d_in[0];   // (B, C, L) f32
    const float* dt = (const float*)d_in[1];   // (B, L)    f32
    const float* kt = (const float*)d_in[2];   // (1, 1, K) f32
    float* out = (float*)d_out;                // (B, C, L) f32

    // Device-function attribute set; not a stream op, graph-capture safe.
    cudaFuncSetAttribute(fused_kernel,
                         cudaFuncAttributeMaxDynamicSharedMemorySize, SMEM_BYTES);

    compute_w_kernel<<<(Bv * Lv + 255) / 256, 256>>>(dt);
    fused_kernel<<<Bv * Cv, 256, SMEM_BYTES>>>(x, kt, out);
}